// round 15
// baseline (speedup 1.0000x reference)
#include <cuda_runtime.h>
#include <cuda_bf16.h>
#include <stdint.h>
#include <math.h>

#define B_    2
#define H_    16
#define NTOK  8192
#define D_    128
#define G_    8
#define P_    1024
#define MK_   34
#define S_    (G_*MK_)
#define BH_   (B_*H_)

#define SCALE_F 0.08838834764831843f
#define LN8_F   2.0794415416798357f
#define TINY_F  1.17549435e-38f
#define EPS_F   1.1920929e-07f

// smem u32 offsets (split hi/lo arrays; OX/red alias dead regions at epilogue)
#define U_QH 0
#define U_QL 4096
#define U_KH 8192
#define U_KL 12288
#define U_VH 16384
#define U_VL 20480
#define SMEM_U 24576
#define SMEM_B (SMEM_U*4)

__device__ __align__(16) float g_qrep [BH_*P_*D_];
__device__ __align__(16) float g_krep [BH_*P_*D_];
__device__ __align__(16) float g_vmean[BH_*P_*D_];
__device__ __align__(16) float g_attn1[BH_*P_*D_];
__device__ __align__(16) float g_adel [BH_*P_*D_];
__device__ __align__(16) float g_aadd [BH_*P_*D_];
__device__ float g_lse1[BH_*P_];
__device__ float g_ldel[BH_*P_];
__device__ float g_ladd[BH_*P_];
__device__ float g_score_k[BH_*G_*P_];
__device__ float g_score_q[BH_*G_*P_];
__device__ int   g_kidx[BH_*G_*MK_];
__device__ int   g_qidx[BH_*G_*MK_];
__device__ __align__(16) float g_ksub   [BH_*S_*D_];
__device__ __align__(16) float g_krepsub[BH_*S_*D_];
__device__ __align__(16) float g_vsub   [BH_*S_*D_];
__device__ __align__(16) float g_qsub   [BH_*S_*D_];
__device__ __align__(16) float g_a2     [BH_*S_*D_];
__device__ float g_l2[BH_*S_];
__device__ __align__(16) float g_part_o[(size_t)8*BH_*320*D_];
__device__ float g_part_l[8*BH_*320];

__device__ __forceinline__ void split2(float x0, float x1, uint32_t& hp, uint32_t& lp) {
  __nv_bfloat162 h = __floats2bfloat162_rn(x0, x1);
  hp = *reinterpret_cast<uint32_t*>(&h);
  float h0 = __uint_as_float(hp << 16);
  float h1 = __uint_as_float(hp & 0xffff0000u);
  __nv_bfloat162 l = __floats2bfloat162_rn(x0 - h0, x1 - h1);
  lp = *reinterpret_cast<uint32_t*>(&l);
}

#define MMAB(d,a,b0,b1) \
  asm volatile("mma.sync.aligned.m16n8k16.row.col.f32.bf16.bf16.f32 " \
  "{%0,%1,%2,%3},{%4,%5,%6,%7},{%8,%9},{%0,%1,%2,%3};" \
  : "+f"((d)[0]),"+f"((d)[1]),"+f"((d)[2]),"+f"((d)[3]) \
  : "r"((a)[0]),"r"((a)[1]),"r"((a)[2]),"r"((a)[3]),"r"(b0),"r"(b1))

// ---------------- threefry2x32 ----------------
__device__ __forceinline__ void threefry2x32(uint32_t k0, uint32_t k1,
                                             uint32_t x0, uint32_t x1,
                                             uint32_t& o0, uint32_t& o1) {
  uint32_t k2 = k0 ^ k1 ^ 0x1BD11BDAu;
  x0 += k0; x1 += k1;
#define TFR(r) { x0 += x1; x1 = (x1 << (r)) | (x1 >> (32 - (r))); x1 ^= x0; }
  TFR(13) TFR(15) TFR(26) TFR(6)   x0 += k1; x1 += k2 + 1u;
  TFR(17) TFR(29) TFR(16) TFR(24)  x0 += k2; x1 += k0 + 2u;
  TFR(13) TFR(15) TFR(26) TFR(6)   x0 += k0; x1 += k1 + 3u;
  TFR(17) TFR(29) TFR(16) TFR(24)  x0 += k1; x1 += k2 + 4u;
  TFR(13) TFR(15) TFR(26) TFR(6)   x0 += k2; x1 += k0 + 5u;
#undef TFR
  o0 = x0; o1 = x1;
}

// ---------------- fused means + scores ----------------
__global__ void __launch_bounds__(256) prep_kernel(const float* __restrict__ q,
                                                   const float* __restrict__ k,
                                                   const float* __restrict__ v) {
  int wid = (blockIdx.x*256 + threadIdx.x) >> 5;
  int lane = threadIdx.x & 31;
  int bh = wid >> 10, j = wid & 1023;
  size_t base = (((size_t)bh*NTOK) << 7) + (((size_t)j) << 7) + lane*4;
  size_t rbase = ((((size_t)bh*P_) + j) << 7) + lane*4;
  float4 rows[8];
  float kss = 0.f, qss = 0.f;

  float4 mn = make_float4(0,0,0,0);
#pragma unroll
  for (int g = 0; g < 8; g++) {
    rows[g] = *(const float4*)(k + base + ((size_t)g*P_ << 7));
    mn.x+=rows[g].x; mn.y+=rows[g].y; mn.z+=rows[g].z; mn.w+=rows[g].w;
  }
  mn.x*=0.125f; mn.y*=0.125f; mn.z*=0.125f; mn.w*=0.125f;
  *(float4*)(g_krep + rbase) = mn;
#pragma unroll
  for (int g = 0; g < 8; g++) {
    float dx=rows[g].x-mn.x, dy=rows[g].y-mn.y, dz=rows[g].z-mn.z, dw=rows[g].w-mn.w;
    float ss = dx*dx + dy*dy + dz*dz + dw*dw;
#pragma unroll
    for (int off = 16; off; off >>= 1) ss += __shfl_xor_sync(0xffffffffu, ss, off);
    if (lane == g) kss = ss;
  }
  mn = make_float4(0,0,0,0);
#pragma unroll
  for (int g = 0; g < 8; g++) {
    rows[g] = *(const float4*)(q + base + ((size_t)g*P_ << 7));
    mn.x+=rows[g].x; mn.y+=rows[g].y; mn.z+=rows[g].z; mn.w+=rows[g].w;
  }
  mn.x*=0.125f; mn.y*=0.125f; mn.z*=0.125f; mn.w*=0.125f;
  *(float4*)(g_qrep + rbase) = mn;
#pragma unroll
  for (int g = 0; g < 8; g++) {
    float dx=rows[g].x-mn.x, dy=rows[g].y-mn.y, dz=rows[g].z-mn.z, dw=rows[g].w-mn.w;
    float ss = dx*dx + dy*dy + dz*dz + dw*dw;
#pragma unroll
    for (int off = 16; off; off >>= 1) ss += __shfl_xor_sync(0xffffffffu, ss, off);
    if (lane == 8 + g) qss = ss;
  }
  mn = make_float4(0,0,0,0);
#pragma unroll
  for (int g = 0; g < 8; g++) {
    float4 r = *(const float4*)(v + base + ((size_t)g*P_ << 7));
    mn.x+=r.x; mn.y+=r.y; mn.z+=r.z; mn.w+=r.w;
  }
  mn.x*=0.125f; mn.y*=0.125f; mn.z*=0.125f; mn.w*=0.125f;
  *(float4*)(g_vmean + rbase) = mn;

  if (lane < 16) {
    int t = lane >> 3, g = lane & 7;
    float ss = t ? qss : kss;
    unsigned r = (unsigned)(bh*8192 + g*1024 + j);
    uint32_t rk0, rk1, o0, o1;
    threefry2x32(0u, 42u, 0u, (uint32_t)t, rk0, rk1);
    threefry2x32(rk0, rk1, 0u, r, o0, o1);
    uint32_t bits = o0 ^ o1;
    float u = __uint_as_float((bits >> 9) | 0x3f800000u) - 1.0f;
    if (u <= 0.0f) u = TINY_F;
    float gum = -logf(-logf(u));
    float score = logf(sqrtf(ss) * 100.0f + EPS_F) + gum;
    (t ? g_score_q : g_score_k)[r] = score;
  }
}

// ---------------- top-34 ----------------
__global__ void __launch_bounds__(256) topk_kernel() {
  int grp = blockIdx.x;
  int t   = blockIdx.y;
  float* sc = (t ? g_score_q : g_score_k) + (size_t)grp * P_;
  int*  out = (t ? g_qidx    : g_kidx   ) + (size_t)grp * MK_;
  __shared__ float sv[1024];
  __shared__ float rv[256];
  __shared__ int   ri[256];
  int tid = threadIdx.x;
#pragma unroll
  for (int r = 0; r < 4; r++) sv[tid + 256*r] = sc[tid + 256*r];
  __syncthreads();
  for (int it = 0; it < MK_; it++) {
    float bv = -INFINITY; int bi = 0x7fffffff;
#pragma unroll
    for (int r = 0; r < 4; r++) {
      int i = tid + 256*r;
      float vv = sv[i];
      if (vv > bv || (vv == bv && i < bi)) { bv = vv; bi = i; }
    }
    rv[tid] = bv; ri[tid] = bi;
    __syncthreads();
    for (int s = 128; s; s >>= 1) {
      if (tid < s) {
        float vv = rv[tid+s]; int i2 = ri[tid+s];
        if (vv > rv[tid] || (vv == rv[tid] && i2 < ri[tid])) { rv[tid]=vv; ri[tid]=i2; }
      }
      __syncthreads();
    }
    if (tid == 0) { out[it] = ri[0]; sv[ri[0]] = -INFINITY; }
    __syncthreads();
  }
}

// ---------------- gathers ----------------
__global__ void __launch_bounds__(256) gather_kernel(const float* __restrict__ q,
                                                     const float* __restrict__ k,
                                                     const float* __restrict__ v) {
  unsigned wi = (blockIdx.x * 256u + threadIdx.x) >> 5;
  int lane = threadIdx.x & 31;
  if (wi >= (unsigned)(BH_*S_)) return;
  int bh = wi / S_;
  int rr = wi % S_;
  int g = rr / MK_, tt = rr % MK_;
  int kj = g_kidx[(bh*G_+g)*MK_+tt];
  int qj = g_qidx[(bh*G_+g)*MK_+tt];
  size_t srck = ((size_t)bh*NTOK + g*P_ + kj) << 7;
  size_t srcq = ((size_t)bh*NTOK + g*P_ + qj) << 7;
  size_t dst  = ((size_t)wi << 7) + lane*4;
  *(float4*)(g_ksub    + dst) = *(const float4*)(k + srck + lane*4);
  *(float4*)(g_vsub    + dst) = *(const float4*)(v + srck + lane*4);
  *(float4*)(g_krepsub + dst) = *(const float4*)(g_krep + (((size_t)bh*P_ + kj) << 7) + lane*4);
  *(float4*)(g_qsub    + dst) = *(const float4*)(q + srcq + lane*4);
}

// ---------------- bf16x3 mma flash attention, P in registers ----------------
// per bh: j in [0,20) p2 (sp=j/5 of 4 splits, qb=j%5); [20,36) p0; [36,52) p1-del; [52,68) p1-add
__global__ void __launch_bounds__(256, 2)
attn_bf16_kernel(const float* __restrict__ kin, const float* __restrict__ vin) {
  extern __shared__ uint32_t su[];
  uint32_t* Qh = su + U_QH; uint32_t* Ql = su + U_QL;
  uint32_t* Kh = su + U_KH; uint32_t* Kl = su + U_KL;
  uint32_t* Vth = su + U_VH; uint32_t* Vtl = su + U_VL;

  int tid = threadIdx.x;
  int w = tid >> 5, lane = tid & 31;
  int gr = lane >> 2, gc = lane & 3;
  int wq = w >> 1, wk = w & 1;
  int cx3 = gr & 3;

  int bh = blockIdx.x / 68;
  int j  = blockIdx.x % 68;
  int mode, qb, sp = 0;
  if (j < 20) { mode = 3; sp = j / 5; qb = j % 5; }
  else { mode = (j - 20) >> 4; qb = (j - 20) & 15; }

  const float *Qs, *Ks, *Vs; float *dO, *dL;
  int nq, ke, ntile, k0;
  if (mode == 0) { Qs=g_qrep+(size_t)bh*P_*D_; Ks=g_krep+(size_t)bh*P_*D_;  Vs=g_vmean+(size_t)bh*P_*D_;
                   nq=P_; ke=P_; ntile=16; k0=0; dO=g_attn1; dL=g_lse1; }
  else if (mode==1){Qs=g_qrep+(size_t)bh*P_*D_; Ks=g_krepsub+(size_t)bh*S_*D_; Vs=g_vsub+(size_t)bh*S_*D_;
                   nq=P_; ke=S_; ntile=5; k0=0; dO=g_adel; dL=g_ldel; }
  else if (mode==2){Qs=g_qrep+(size_t)bh*P_*D_; Ks=g_ksub+(size_t)bh*S_*D_;  Vs=g_vsub+(size_t)bh*S_*D_;
                   nq=P_; ke=S_; ntile=5; k0=0; dO=g_aadd; dL=g_ladd; }
  else           { Qs=g_qsub+(size_t)bh*S_*D_; Ks=kin+(size_t)bh*NTOK*D_;   Vs=vin+(size_t)bh*NTOK*D_;
                   nq=S_; k0=sp*2048; ke=k0+2048; ntile=32; dO=0; dL=0; }
  int q0 = qb * 64;

  // ---- stage Q hi/lo ----
#pragma unroll
  for (int t = 0; t < 8; t++) {
    int lin = tid + t*256;
    int row = lin >> 5, c4 = lin & 31;
    int gq = q0 + row; if (gq > nq-1) gq = nq-1;
    float4 v = *(const float4*)(Qs + ((size_t)gq << 7) + c4*4);
    v.x*=SCALE_F; v.y*=SCALE_F; v.z*=SCALE_F; v.w*=SCALE_F;
    uint32_t hp0,lp0,hp1,lp1;
    split2(v.x, v.y, hp0, lp0);
    split2(v.z, v.w, hp1, lp1);
    int r7 = row & 7;
    int j0 = 2*c4, j1 = j0+1;
    int col0 = (((j0>>3) ^ r7)<<3) + ((j0&3)<<1) + ((j0>>2)&1);
    int col1 = (((j1>>3) ^ r7)<<3) + ((j1&3)<<1) + ((j1>>2)&1);
    Qh[row*64+col0]=hp0; Ql[row*64+col0]=lp0;
    Qh[row*64+col1]=hp1; Ql[row*64+col1]=lp1;
  }

  float oacc[16][4];
#pragma unroll
  for (int n=0;n<16;n++)
#pragma unroll
    for (int t=0;t<4;t++) oacc[n][t]=0.f;
  float psum[2] = {0.f, 0.f};

  int r0 = wq*16 + gr;

  for (int tile = 0; tile < ntile; tile++) {
    int kb = k0 + tile*64;
    __syncthreads();
#pragma unroll
    for (int t = 0; t < 8; t++) {
      int lin = tid + t*256;
      int row = lin >> 5, c4 = lin & 31;
      int gk = kb + row;
      float4 v = make_float4(0,0,0,0);
      if (gk < ke) v = *(const float4*)(Ks + ((size_t)gk << 7) + c4*4);
      uint32_t hp0,lp0,hp1,lp1;
      split2(v.x, v.y, hp0, lp0);
      split2(v.z, v.w, hp1, lp1);
      int r7 = row & 7;
      int j0 = 2*c4, j1 = j0+1;
      int col0 = (((j0>>3) ^ r7)<<3) + ((j0&3)<<1) + ((j0>>2)&1);
      int col1 = (((j1>>3) ^ r7)<<3) + ((j1&3)<<1) + ((j1>>2)&1);
      Kh[row*64+col0]=hp0; Kl[row*64+col0]=lp0;
      Kh[row*64+col1]=hp1; Kl[row*64+col1]=lp1;
    }
#pragma unroll
    for (int t = 0; t < 4; t++) {
      int lin = tid + t*256;
      int kp = lin & 31, dg = lin >> 5;
      int d0 = dg*4;
      int ka = kb + 2*kp;
      float4 va = make_float4(0,0,0,0), vb = va;
      if (ka   < ke) va = *(const float4*)(Vs + ((size_t)ka << 7) + d0);
      if (ka+1 < ke) vb = *(const float4*)(Vs + ((size_t)(ka+1) << 7) + d0);
      int cc = kp>>3, gg = kp&3, hh = (kp>>2)&1;
      uint32_t hp, lp;
      split2(va.x, vb.x, hp, lp);
      Vth[(d0+0)*32 + (((cc^0)<<3)+(gg<<1)+hh)] = hp; Vtl[(d0+0)*32 + (((cc^0)<<3)+(gg<<1)+hh)] = lp;
      split2(va.y, vb.y, hp, lp);
      Vth[(d0+1)*32 + (((cc^1)<<3)+(gg<<1)+hh)] = hp; Vtl[(d0+1)*32 + (((cc^1)<<3)+(gg<<1)+hh)] = lp;
      split2(va.z, vb.z, hp, lp);
      Vth[(d0+2)*32 + (((cc^2)<<3)+(gg<<1)+hh)] = hp; Vtl[(d0+2)*32 + (((cc^2)<<3)+(gg<<1)+hh)] = lp;
      split2(va.w, vb.w, hp, lp);
      Vth[(d0+3)*32 + (((cc^3)<<3)+(gg<<1)+hh)] = hp; Vtl[(d0+3)*32 + (((cc^3)<<3)+(gg<<1)+hh)] = lp;
    }
    __syncthreads();

    // ---- S = Q K^T (16q x 32k per warp, 3-pass) ----
    float sacc[4][4];
#pragma unroll
    for (int n=0;n<4;n++)
#pragma unroll
      for (int t=0;t<4;t++) sacc[n][t]=0.f;
#pragma unroll
    for (int c = 0; c < 8; c++) {
      int cq = ((c ^ gr) << 3) + (gc << 1);
      uint2 a0h = *(const uint2*)(Qh + (r0  )*64 + cq);
      uint2 a1h = *(const uint2*)(Qh + (r0+8)*64 + cq);
      uint2 a0l = *(const uint2*)(Ql + (r0  )*64 + cq);
      uint2 a1l = *(const uint2*)(Ql + (r0+8)*64 + cq);
      uint32_t Ah[4] = {a0h.x, a1h.x, a0h.y, a1h.y};
      uint32_t Al[4] = {a0l.x, a1l.x, a0l.y, a1l.y};
#pragma unroll
      for (int nn = 0; nn < 4; nn++) {
        int nb = wk*32 + nn*8 + gr;
        uint2 bh2 = *(const uint2*)(Kh + nb*64 + cq);
        uint2 bl2 = *(const uint2*)(Kl + nb*64 + cq);
        MMAB(sacc[nn], Ah, bh2.x, bh2.y);
        MMAB(sacc[nn], Ah, bl2.x, bl2.y);
        MMAB(sacc[nn], Al, bh2.x, bh2.y);
      }
    }

    // ---- exp in registers -> P fragments (natural order IS A-frag order) ----
    uint32_t Phi[2][4], Plo[2][4];
#pragma unroll
    for (int kc = 0; kc < 2; kc++) {
#pragma unroll
      for (int hh = 0; hh < 2; hh++) {
        int nn = 2*kc + hh;
        int colb = kb + wk*32 + nn*8 + 2*gc;
        float p0 = (colb   < ke) ? __expf(sacc[nn][0]) : 0.f;
        float p1 = (colb+1 < ke) ? __expf(sacc[nn][1]) : 0.f;
        float p2 = (colb   < ke) ? __expf(sacc[nn][2]) : 0.f;
        float p3 = (colb+1 < ke) ? __expf(sacc[nn][3]) : 0.f;
        psum[0] += p0 + p1;
        psum[1] += p2 + p3;
        split2(p0, p1, Phi[kc][2*hh+0], Plo[kc][2*hh+0]);
        split2(p2, p3, Phi[kc][2*hh+1], Plo[kc][2*hh+1]);
      }
    }

    // ---- O += P V (partial over this warp's 32 keys, 3-pass) ----
#pragma unroll
    for (int kc = 0; kc < 2; kc++) {
      int c2 = wk*2 + kc;
      int cp = (((c2 ^ cx3) & 3) << 3) + (gc << 1);
#pragma unroll
      for (int n = 0; n < 16; n++) {
        int dn = n*8 + gr;
        uint2 vh = *(const uint2*)(Vth + dn*32 + cp);
        uint2 vl = *(const uint2*)(Vtl + dn*32 + cp);
        MMAB(oacc[n], Phi[kc], vh.x, vh.y);
        MMAB(oacc[n], Phi[kc], vl.x, vl.y);
        MMAB(oacc[n], Plo[kc], vh.x, vh.y);
      }
    }
  }

  // ---- cross-wk reduction + epilogue ----
  psum[0] += __shfl_xor_sync(0xffffffffu, psum[0], 1);
  psum[0] += __shfl_xor_sync(0xffffffffu, psum[0], 2);
  psum[1] += __shfl_xor_sync(0xffffffffu, psum[1], 1);
  psum[1] += __shfl_xor_sync(0xffffffffu, psum[1], 2);
  __syncthreads();
  float* OX  = (float*)su;               // 64 x 132 (aliases dead Q/K head)
  float* red = (float*)(su + U_VH);      // 2 x 64   (aliases dead V)
  if (wk == 1) {
#pragma unroll
    for (int n = 0; n < 16; n++) {
      int col = n*8 + 2*gc;
      *(float2*)(OX + (r0  )*132 + col) = make_float2(oacc[n][0], oacc[n][1]);
      *(float2*)(OX + (r0+8)*132 + col) = make_float2(oacc[n][2], oacc[n][3]);
    }
  }
  if (gc == 0) {
    red[wk*64 + r0]     = psum[0];
    red[wk*64 + r0 + 8] = psum[1];
  }
  __syncthreads();
  if (wk == 0) {
    float L0 = red[r0]     + red[64 + r0];
    float L1 = red[r0 + 8] + red[64 + r0 + 8];
#pragma unroll
    for (int n = 0; n < 16; n++) {
      int col = n*8 + 2*gc;
      float2 x0 = *(const float2*)(OX + (r0  )*132 + col);
      float2 x1 = *(const float2*)(OX + (r0+8)*132 + col);
      oacc[n][0] += x0.x; oacc[n][1] += x0.y;
      oacc[n][2] += x1.x; oacc[n][3] += x1.y;
    }
    if (mode < 3) {
      float iv0 = 1.0f / L0, iv1 = 1.0f / L1;
#pragma unroll
      for (int n = 0; n < 16; n++) {
        int col = n*8 + 2*gc;
        *(float2*)(dO + (((size_t)bh*nq + q0 + r0  ) << 7) + col) =
            make_float2(oacc[n][0]*iv0, oacc[n][1]*iv0);
        *(float2*)(dO + (((size_t)bh*nq + q0 + r0+8) << 7) + col) =
            make_float2(oacc[n][2]*iv1, oacc[n][3]*iv1);
      }
      if (gc == 0) {
        dL[(size_t)bh*nq + q0 + r0]     = logf(L0);
        dL[(size_t)bh*nq + q0 + r0 + 8] = logf(L1);
      }
    } else {
      size_t pb = (size_t)(sp*BH_ + bh)*320 + q0;
#pragma unroll
      for (int n = 0; n < 16; n++) {
        int col = n*8 + 2*gc;
        *(float2*)(g_part_o + ((pb + r0  ) << 7) + col) = make_float2(oacc[n][0], oacc[n][1]);
        *(float2*)(g_part_o + ((pb + r0+8) << 7) + col) = make_float2(oacc[n][2], oacc[n][3]);
      }
      if (gc == 0) {
        g_part_l[pb + r0]     = L0;
        g_part_l[pb + r0 + 8] = L1;
      }
    }
  }
}

// ---------------- p2 merge (4 splits) ----------------
__global__ void __launch_bounds__(256) merge3_kernel() {
  int bh = blockIdx.y;
  int w = threadIdx.x >> 5, lane = threadIdx.x & 31;
  int row = blockIdx.x*8 + w;
  if (row >= S_) return;
  float L = 0.f;
  float4 o = make_float4(0,0,0,0);
#pragma unroll
  for (int s = 0; s < 4; s++) {
    size_t ri = (size_t)(s*BH_ + bh)*320 + row;
    L += g_part_l[ri];
    float4 po = *(const float4*)(g_part_o + (ri << 7) + lane*4);
    o.x += po.x; o.y += po.y; o.z += po.z; o.w += po.w;
  }
  float inv = 1.0f / L;
  o.x*=inv; o.y*=inv; o.z*=inv; o.w*=inv;
  *(float4*)(g_a2 + (((size_t)bh*S_ + row) << 7) + lane*4) = o;
  if (lane == 0) g_l2[(size_t)bh*S_ + row] = logf(L);
}

// ---------------- p1 combine + broadcast ----------------
__global__ void __launch_bounds__(256) combine_kernel(float* __restrict__ out, int has_lse) {
  unsigned wi = (blockIdx.x * 256u + threadIdx.x) >> 5;
  int lane = threadIdx.x & 31;
  int bh = wi >> 10, j = wi & 1023;
  float l1 = g_lse1[wi] + LN8_F;
  float ld = g_ldel[wi];
  float la = g_ladd[wi];
  float c1 = expf(ld - l1);
  float inv1 = 1.0f / (1.0f - c1);
  float lp1 = l1 + log1pf(-c1);
  float c2 = 1.0f / (1.0f + expf(la - lp1));
  float lse = fmaxf(lp1, la) + log1pf(expf(-fabsf(lp1 - la)));
  size_t off = ((size_t)wi << 7) + lane*4;
  float4 a0 = *(const float4*)(g_attn1 + off);
  float4 ad = *(const float4*)(g_adel + off);
  float4 aa = *(const float4*)(g_aadd + off);
  float4 r;
  float c2b = 1.0f - c2;
  r.x = c2*((a0.x - c1*ad.x)*inv1) + c2b*aa.x;
  r.y = c2*((a0.y - c1*ad.y)*inv1) + c2b*aa.y;
  r.z = c2*((a0.z - c1*ad.z)*inv1) + c2b*aa.z;
  r.w = c2*((a0.w - c1*ad.w)*inv1) + c2b*aa.w;
  float* outl = out + (size_t)BH_*NTOK*D_;
#pragma unroll
  for (int g = 0; g < G_; g++) {
    size_t orow = (size_t)bh*NTOK + g*P_ + j;
    *(float4*)(out + (orow << 7) + lane*4) = r;
    if (lane == 0 && has_lse) outl[orow] = lse;
  }
}

// ---------------- p2 scatter ----------------
__global__ void __launch_bounds__(256) scatter_kernel(float* __restrict__ out, int has_lse) {
  unsigned wi = (blockIdx.x * 256u + threadIdx.x) >> 5;
  int lane = threadIdx.x & 31;
  if (wi >= (unsigned)(BH_*S_)) return;
  int bh = wi / S_;
  int rr = wi % S_;
  int g = rr / MK_, tt = rr % MK_;
  int qj = g_qidx[(bh*G_+g)*MK_+tt];
  size_t orow = (size_t)bh*NTOK + g*P_ + qj;
  float4 a = *(const float4*)(g_a2 + ((size_t)wi << 7) + lane*4);
  *(float4*)(out + (orow << 7) + lane*4) = a;
  if (lane == 0 && has_lse) out[(size_t)BH_*NTOK*D_ + orow] = g_l2[wi];
}

// ---------------- launch ----------------
extern "C" void kernel_launch(void* const* d_in, const int* in_sizes, int n_in,
                              void* d_out, int out_size) {
  const float* q = (const float*)d_in[0];
  const float* k = (const float*)d_in[1];
  const float* v = (const float*)d_in[2];
  float* out = (float*)d_out;
  int has_lse = (out_size >= BH_*NTOK*(D_ + 1)) ? 1 : 0;

  cudaFuncSetAttribute(attn_bf16_kernel,
                       cudaFuncAttributeMaxDynamicSharedMemorySize, SMEM_B);

  prep_kernel  <<<4096, 256>>>(q, k, v);
  topk_kernel  <<<dim3(BH_*G_, 2), 256>>>();
  gather_kernel<<<(BH_*S_*32 + 255)/256, 256>>>(q, k, v);

  attn_bf16_kernel<<<68*BH_, 256, SMEM_B>>>(k, v);
  merge3_kernel <<<dim3((S_+7)/8, BH_), 256>>>();

  combine_kernel<<<(BH_*P_*32)/256, 256>>>(out, has_lse);
  scatter_kernel<<<(BH_*S_*32 + 255)/256, 256>>>(out, has_lse);
}

// round 16
// speedup vs baseline: 1.6021x; 1.6021x over previous
#include <cuda_runtime.h>
#include <cuda_bf16.h>
#include <stdint.h>
#include <math.h>

#define B_    2
#define H_    16
#define NTOK  8192
#define D_    128
#define G_    8
#define P_    1024
#define MK_   34
#define S_    (G_*MK_)
#define BH_   (B_*H_)

#define SCALE_F 0.08838834764831843f
#define LN8_F   2.0794415416798357f
#define TINY_F  1.17549435e-38f
#define EPS_F   1.1920929e-07f

// smem u32 offsets (split hi/lo arrays; OX/red alias dead regions at epilogue)
#define U_QH 0
#define U_QL 4096
#define U_KH 8192
#define U_KL 12288
#define U_VH 16384
#define U_VL 20480
#define SMEM_U 24576
#define SMEM_B (SMEM_U*4)

__device__ __align__(16) float g_qrep [BH_*P_*D_];
__device__ __align__(16) float g_krep [BH_*P_*D_];
__device__ __align__(16) float g_vmean[BH_*P_*D_];
__device__ __align__(16) float g_attn1[BH_*P_*D_];
__device__ __align__(16) float g_adel [BH_*P_*D_];
__device__ __align__(16) float g_aadd [BH_*P_*D_];
__device__ float g_lse1[BH_*P_];
__device__ float g_ldel[BH_*P_];
__device__ float g_ladd[BH_*P_];
__device__ float g_score_k[BH_*G_*P_];
__device__ float g_score_q[BH_*G_*P_];
__device__ int   g_kidx[BH_*G_*MK_];
__device__ int   g_qidx[BH_*G_*MK_];
__device__ __align__(16) float g_ksub   [BH_*S_*D_];
__device__ __align__(16) float g_krepsub[BH_*S_*D_];
__device__ __align__(16) float g_vsub   [BH_*S_*D_];
__device__ __align__(16) float g_qsub   [BH_*S_*D_];
__device__ float g_l2[BH_*S_];
__device__ __align__(16) float g_part_o[(size_t)8*BH_*320*D_];
__device__ float g_part_l[8*BH_*320];

__device__ __forceinline__ void split2(float x0, float x1, uint32_t& hp, uint32_t& lp) {
  __nv_bfloat162 h = __floats2bfloat162_rn(x0, x1);
  hp = *reinterpret_cast<uint32_t*>(&h);
  float h0 = __uint_as_float(hp << 16);
  float h1 = __uint_as_float(hp & 0xffff0000u);
  __nv_bfloat162 l = __floats2bfloat162_rn(x0 - h0, x1 - h1);
  lp = *reinterpret_cast<uint32_t*>(&l);
}

#define MMAB(d,a,b0,b1) \
  asm volatile("mma.sync.aligned.m16n8k16.row.col.f32.bf16.bf16.f32 " \
  "{%0,%1,%2,%3},{%4,%5,%6,%7},{%8,%9},{%0,%1,%2,%3};" \
  : "+f"((d)[0]),"+f"((d)[1]),"+f"((d)[2]),"+f"((d)[3]) \
  : "r"((a)[0]),"r"((a)[1]),"r"((a)[2]),"r"((a)[3]),"r"(b0),"r"(b1))

// ---------------- threefry2x32 ----------------
__device__ __forceinline__ void threefry2x32(uint32_t k0, uint32_t k1,
                                             uint32_t x0, uint32_t x1,
                                             uint32_t& o0, uint32_t& o1) {
  uint32_t k2 = k0 ^ k1 ^ 0x1BD11BDAu;
  x0 += k0; x1 += k1;
#define TFR(r) { x0 += x1; x1 = (x1 << (r)) | (x1 >> (32 - (r))); x1 ^= x0; }
  TFR(13) TFR(15) TFR(26) TFR(6)   x0 += k1; x1 += k2 + 1u;
  TFR(17) TFR(29) TFR(16) TFR(24)  x0 += k2; x1 += k0 + 2u;
  TFR(13) TFR(15) TFR(26) TFR(6)   x0 += k0; x1 += k1 + 3u;
  TFR(17) TFR(29) TFR(16) TFR(24)  x0 += k1; x1 += k2 + 4u;
  TFR(13) TFR(15) TFR(26) TFR(6)   x0 += k2; x1 += k0 + 5u;
#undef TFR
  o0 = x0; o1 = x1;
}

// ---------------- fused means + scores ----------------
__global__ void __launch_bounds__(256) prep_kernel(const float* __restrict__ q,
                                                   const float* __restrict__ k,
                                                   const float* __restrict__ v) {
  int wid = (blockIdx.x*256 + threadIdx.x) >> 5;
  int lane = threadIdx.x & 31;
  int bh = wid >> 10, j = wid & 1023;
  size_t base = (((size_t)bh*NTOK) << 7) + (((size_t)j) << 7) + lane*4;
  size_t rbase = ((((size_t)bh*P_) + j) << 7) + lane*4;
  float4 rows[8];
  float kss = 0.f, qss = 0.f;

  float4 mn = make_float4(0,0,0,0);
#pragma unroll
  for (int g = 0; g < 8; g++) {
    rows[g] = *(const float4*)(k + base + ((size_t)g*P_ << 7));
    mn.x+=rows[g].x; mn.y+=rows[g].y; mn.z+=rows[g].z; mn.w+=rows[g].w;
  }
  mn.x*=0.125f; mn.y*=0.125f; mn.z*=0.125f; mn.w*=0.125f;
  *(float4*)(g_krep + rbase) = mn;
#pragma unroll
  for (int g = 0; g < 8; g++) {
    float dx=rows[g].x-mn.x, dy=rows[g].y-mn.y, dz=rows[g].z-mn.z, dw=rows[g].w-mn.w;
    float ss = dx*dx + dy*dy + dz*dz + dw*dw;
#pragma unroll
    for (int off = 16; off; off >>= 1) ss += __shfl_xor_sync(0xffffffffu, ss, off);
    if (lane == g) kss = ss;
  }
  mn = make_float4(0,0,0,0);
#pragma unroll
  for (int g = 0; g < 8; g++) {
    rows[g] = *(const float4*)(q + base + ((size_t)g*P_ << 7));
    mn.x+=rows[g].x; mn.y+=rows[g].y; mn.z+=rows[g].z; mn.w+=rows[g].w;
  }
  mn.x*=0.125f; mn.y*=0.125f; mn.z*=0.125f; mn.w*=0.125f;
  *(float4*)(g_qrep + rbase) = mn;
#pragma unroll
  for (int g = 0; g < 8; g++) {
    float dx=rows[g].x-mn.x, dy=rows[g].y-mn.y, dz=rows[g].z-mn.z, dw=rows[g].w-mn.w;
    float ss = dx*dx + dy*dy + dz*dz + dw*dw;
#pragma unroll
    for (int off = 16; off; off >>= 1) ss += __shfl_xor_sync(0xffffffffu, ss, off);
    if (lane == 8 + g) qss = ss;
  }
  mn = make_float4(0,0,0,0);
#pragma unroll
  for (int g = 0; g < 8; g++) {
    float4 r = *(const float4*)(v + base + ((size_t)g*P_ << 7));
    mn.x+=r.x; mn.y+=r.y; mn.z+=r.z; mn.w+=r.w;
  }
  mn.x*=0.125f; mn.y*=0.125f; mn.z*=0.125f; mn.w*=0.125f;
  *(float4*)(g_vmean + rbase) = mn;

  if (lane < 16) {
    int t = lane >> 3, g = lane & 7;
    float ss = t ? qss : kss;
    unsigned r = (unsigned)(bh*8192 + g*1024 + j);
    uint32_t rk0, rk1, o0, o1;
    threefry2x32(0u, 42u, 0u, (uint32_t)t, rk0, rk1);
    threefry2x32(rk0, rk1, 0u, r, o0, o1);
    uint32_t bits = o0 ^ o1;
    float u = __uint_as_float((bits >> 9) | 0x3f800000u) - 1.0f;
    if (u <= 0.0f) u = TINY_F;
    float gum = -logf(-logf(u));
    float score = logf(sqrtf(ss) * 100.0f + EPS_F) + gum;
    (t ? g_score_q : g_score_k)[r] = score;
  }
}

// ---------------- top-34 ----------------
__global__ void __launch_bounds__(256) topk_kernel() {
  int grp = blockIdx.x;
  int t   = blockIdx.y;
  float* sc = (t ? g_score_q : g_score_k) + (size_t)grp * P_;
  int*  out = (t ? g_qidx    : g_kidx   ) + (size_t)grp * MK_;
  __shared__ float sv[1024];
  __shared__ float rv[256];
  __shared__ int   ri[256];
  int tid = threadIdx.x;
#pragma unroll
  for (int r = 0; r < 4; r++) sv[tid + 256*r] = sc[tid + 256*r];
  __syncthreads();
  for (int it = 0; it < MK_; it++) {
    float bv = -INFINITY; int bi = 0x7fffffff;
#pragma unroll
    for (int r = 0; r < 4; r++) {
      int i = tid + 256*r;
      float vv = sv[i];
      if (vv > bv || (vv == bv && i < bi)) { bv = vv; bi = i; }
    }
    rv[tid] = bv; ri[tid] = bi;
    __syncthreads();
    for (int s = 128; s; s >>= 1) {
      if (tid < s) {
        float vv = rv[tid+s]; int i2 = ri[tid+s];
        if (vv > rv[tid] || (vv == rv[tid] && i2 < ri[tid])) { rv[tid]=vv; ri[tid]=i2; }
      }
      __syncthreads();
    }
    if (tid == 0) { out[it] = ri[0]; sv[ri[0]] = -INFINITY; }
    __syncthreads();
  }
}

// ---------------- gathers ----------------
__global__ void __launch_bounds__(256) gather_kernel(const float* __restrict__ q,
                                                     const float* __restrict__ k,
                                                     const float* __restrict__ v) {
  unsigned wi = (blockIdx.x * 256u + threadIdx.x) >> 5;
  int lane = threadIdx.x & 31;
  if (wi >= (unsigned)(BH_*S_)) return;
  int bh = wi / S_;
  int rr = wi % S_;
  int g = rr / MK_, tt = rr % MK_;
  int kj = g_kidx[(bh*G_+g)*MK_+tt];
  int qj = g_qidx[(bh*G_+g)*MK_+tt];
  size_t srck = ((size_t)bh*NTOK + g*P_ + kj) << 7;
  size_t srcq = ((size_t)bh*NTOK + g*P_ + qj) << 7;
  size_t dst  = ((size_t)wi << 7) + lane*4;
  *(float4*)(g_ksub    + dst) = *(const float4*)(k + srck + lane*4);
  *(float4*)(g_vsub    + dst) = *(const float4*)(v + srck + lane*4);
  *(float4*)(g_krepsub + dst) = *(const float4*)(g_krep + (((size_t)bh*P_ + kj) << 7) + lane*4);
  *(float4*)(g_qsub    + dst) = *(const float4*)(q + srcq + lane*4);
}

// ---------------- bf16x3 mma flash attention, P in registers ----------------
// per bh: j in [0,40) p2 (sp=j/5, qb=j%5); [40,56) p0; [56,72) p1-del; [72,88) p1-add
__global__ void __launch_bounds__(256, 2)
attn_bf16_kernel(const float* __restrict__ kin, const float* __restrict__ vin) {
  extern __shared__ uint32_t su[];
  uint32_t* Qh = su + U_QH; uint32_t* Ql = su + U_QL;
  uint32_t* Kh = su + U_KH; uint32_t* Kl = su + U_KL;
  uint32_t* Vth = su + U_VH; uint32_t* Vtl = su + U_VL;

  int tid = threadIdx.x;
  int w = tid >> 5, lane = tid & 31;
  int gr = lane >> 2, gc = lane & 3;
  int wq = w >> 1, wk = w & 1;
  int cx3 = gr & 3;

  int bh = blockIdx.x / 88;
  int j  = blockIdx.x % 88;
  int mode, qb, sp = 0;
  if (j < 40) { mode = 3; sp = j / 5; qb = j % 5; }
  else { mode = (j - 40) >> 4; qb = (j - 40) & 15; }

  const float *Qs, *Ks, *Vs; float *dO, *dL;
  int nq, ke, ntile, k0;
  if (mode == 0) { Qs=g_qrep+(size_t)bh*P_*D_; Ks=g_krep+(size_t)bh*P_*D_;  Vs=g_vmean+(size_t)bh*P_*D_;
                   nq=P_; ke=P_; ntile=16; k0=0; dO=g_attn1; dL=g_lse1; }
  else if (mode==1){Qs=g_qrep+(size_t)bh*P_*D_; Ks=g_krepsub+(size_t)bh*S_*D_; Vs=g_vsub+(size_t)bh*S_*D_;
                   nq=P_; ke=S_; ntile=5; k0=0; dO=g_adel; dL=g_ldel; }
  else if (mode==2){Qs=g_qrep+(size_t)bh*P_*D_; Ks=g_ksub+(size_t)bh*S_*D_;  Vs=g_vsub+(size_t)bh*S_*D_;
                   nq=P_; ke=S_; ntile=5; k0=0; dO=g_aadd; dL=g_ladd; }
  else           { Qs=g_qsub+(size_t)bh*S_*D_; Ks=kin+(size_t)bh*NTOK*D_;   Vs=vin+(size_t)bh*NTOK*D_;
                   nq=S_; k0=sp*1024; ke=k0+1024; ntile=16; dO=0; dL=0; }
  int q0 = qb * 64;

  // ---- stage Q hi/lo ----
#pragma unroll
  for (int t = 0; t < 8; t++) {
    int lin = tid + t*256;
    int row = lin >> 5, c4 = lin & 31;
    int gq = q0 + row; if (gq > nq-1) gq = nq-1;
    float4 v = *(const float4*)(Qs + ((size_t)gq << 7) + c4*4);
    v.x*=SCALE_F; v.y*=SCALE_F; v.z*=SCALE_F; v.w*=SCALE_F;
    uint32_t hp0,lp0,hp1,lp1;
    split2(v.x, v.y, hp0, lp0);
    split2(v.z, v.w, hp1, lp1);
    int r7 = row & 7;
    int j0 = 2*c4, j1 = j0+1;
    int col0 = (((j0>>3) ^ r7)<<3) + ((j0&3)<<1) + ((j0>>2)&1);
    int col1 = (((j1>>3) ^ r7)<<3) + ((j1&3)<<1) + ((j1>>2)&1);
    Qh[row*64+col0]=hp0; Ql[row*64+col0]=lp0;
    Qh[row*64+col1]=hp1; Ql[row*64+col1]=lp1;
  }

  float oacc[16][4];
#pragma unroll
  for (int n=0;n<16;n++)
#pragma unroll
    for (int t=0;t<4;t++) oacc[n][t]=0.f;
  float psum[2] = {0.f, 0.f};

  int r0 = wq*16 + gr;

  for (int tile = 0; tile < ntile; tile++) {
    int kb = k0 + tile*64;
    __syncthreads();
#pragma unroll
    for (int t = 0; t < 8; t++) {
      int lin = tid + t*256;
      int row = lin >> 5, c4 = lin & 31;
      int gk = kb + row;
      float4 v = make_float4(0,0,0,0);
      if (gk < ke) v = *(const float4*)(Ks + ((size_t)gk << 7) + c4*4);
      uint32_t hp0,lp0,hp1,lp1;
      split2(v.x, v.y, hp0, lp0);
      split2(v.z, v.w, hp1, lp1);
      int r7 = row & 7;
      int j0 = 2*c4, j1 = j0+1;
      int col0 = (((j0>>3) ^ r7)<<3) + ((j0&3)<<1) + ((j0>>2)&1);
      int col1 = (((j1>>3) ^ r7)<<3) + ((j1&3)<<1) + ((j1>>2)&1);
      Kh[row*64+col0]=hp0; Kl[row*64+col0]=lp0;
      Kh[row*64+col1]=hp1; Kl[row*64+col1]=lp1;
    }
#pragma unroll
    for (int t = 0; t < 4; t++) {
      int lin = tid + t*256;
      int kp = lin & 31, dg = lin >> 5;
      int d0 = dg*4;
      int ka = kb + 2*kp;
      float4 va = make_float4(0,0,0,0), vb = va;
      if (ka   < ke) va = *(const float4*)(Vs + ((size_t)ka << 7) + d0);
      if (ka+1 < ke) vb = *(const float4*)(Vs + ((size_t)(ka+1) << 7) + d0);
      int cc = kp>>3, gg = kp&3, hh = (kp>>2)&1;
      uint32_t hp, lp;
      split2(va.x, vb.x, hp, lp);
      Vth[(d0+0)*32 + (((cc^0)<<3)+(gg<<1)+hh)] = hp; Vtl[(d0+0)*32 + (((cc^0)<<3)+(gg<<1)+hh)] = lp;
      split2(va.y, vb.y, hp, lp);
      Vth[(d0+1)*32 + (((cc^1)<<3)+(gg<<1)+hh)] = hp; Vtl[(d0+1)*32 + (((cc^1)<<3)+(gg<<1)+hh)] = lp;
      split2(va.z, vb.z, hp, lp);
      Vth[(d0+2)*32 + (((cc^2)<<3)+(gg<<1)+hh)] = hp; Vtl[(d0+2)*32 + (((cc^2)<<3)+(gg<<1)+hh)] = lp;
      split2(va.w, vb.w, hp, lp);
      Vth[(d0+3)*32 + (((cc^3)<<3)+(gg<<1)+hh)] = hp; Vtl[(d0+3)*32 + (((cc^3)<<3)+(gg<<1)+hh)] = lp;
    }
    __syncthreads();

    // ---- S = Q K^T (16q x 32k per warp, 3-pass) ----
    float sacc[4][4];
#pragma unroll
    for (int n=0;n<4;n++)
#pragma unroll
      for (int t=0;t<4;t++) sacc[n][t]=0.f;
#pragma unroll
    for (int c = 0; c < 8; c++) {
      int cq = ((c ^ gr) << 3) + (gc << 1);
      uint2 a0h = *(const uint2*)(Qh + (r0  )*64 + cq);
      uint2 a1h = *(const uint2*)(Qh + (r0+8)*64 + cq);
      uint2 a0l = *(const uint2*)(Ql + (r0  )*64 + cq);
      uint2 a1l = *(const uint2*)(Ql + (r0+8)*64 + cq);
      uint32_t Ah[4] = {a0h.x, a1h.x, a0h.y, a1h.y};
      uint32_t Al[4] = {a0l.x, a1l.x, a0l.y, a1l.y};
#pragma unroll
      for (int nn = 0; nn < 4; nn++) {
        int nb = wk*32 + nn*8 + gr;
        uint2 bh2 = *(const uint2*)(Kh + nb*64 + cq);
        uint2 bl2 = *(const uint2*)(Kl + nb*64 + cq);
        MMAB(sacc[nn], Ah, bh2.x, bh2.y);
        MMAB(sacc[nn], Ah, bl2.x, bl2.y);
        MMAB(sacc[nn], Al, bh2.x, bh2.y);
      }
    }

    // ---- exp in registers -> P fragments (natural order IS A-frag order) ----
    uint32_t Phi[2][4], Plo[2][4];
#pragma unroll
    for (int kc = 0; kc < 2; kc++) {
#pragma unroll
      for (int hh = 0; hh < 2; hh++) {
        int nn = 2*kc + hh;
        int colb = kb + wk*32 + nn*8 + 2*gc;
        float p0 = (colb   < ke) ? __expf(sacc[nn][0]) : 0.f;
        float p1 = (colb+1 < ke) ? __expf(sacc[nn][1]) : 0.f;
        float p2 = (colb   < ke) ? __expf(sacc[nn][2]) : 0.f;
        float p3 = (colb+1 < ke) ? __expf(sacc[nn][3]) : 0.f;
        psum[0] += p0 + p1;
        psum[1] += p2 + p3;
        split2(p0, p1, Phi[kc][2*hh+0], Plo[kc][2*hh+0]);
        split2(p2, p3, Phi[kc][2*hh+1], Plo[kc][2*hh+1]);
      }
    }

    // ---- O += P V (partial over this warp's 32 keys, 3-pass) ----
#pragma unroll
    for (int kc = 0; kc < 2; kc++) {
      int c2 = wk*2 + kc;
      int cp = (((c2 ^ cx3) & 3) << 3) + (gc << 1);
#pragma unroll
      for (int n = 0; n < 16; n++) {
        int dn = n*8 + gr;
        uint2 vh = *(const uint2*)(Vth + dn*32 + cp);
        uint2 vl = *(const uint2*)(Vtl + dn*32 + cp);
        MMAB(oacc[n], Phi[kc], vh.x, vh.y);
        MMAB(oacc[n], Phi[kc], vl.x, vl.y);
        MMAB(oacc[n], Plo[kc], vh.x, vh.y);
      }
    }
  }

  // ---- cross-wk reduction + epilogue ----
  psum[0] += __shfl_xor_sync(0xffffffffu, psum[0], 1);
  psum[0] += __shfl_xor_sync(0xffffffffu, psum[0], 2);
  psum[1] += __shfl_xor_sync(0xffffffffu, psum[1], 1);
  psum[1] += __shfl_xor_sync(0xffffffffu, psum[1], 2);
  __syncthreads();
  float* OX  = (float*)su;               // 64 x 132 (aliases dead Q/K head)
  float* red = (float*)(su + U_VH);      // 2 x 64   (aliases dead V)
  if (wk == 1) {
#pragma unroll
    for (int n = 0; n < 16; n++) {
      int col = n*8 + 2*gc;
      *(float2*)(OX + (r0  )*132 + col) = make_float2(oacc[n][0], oacc[n][1]);
      *(float2*)(OX + (r0+8)*132 + col) = make_float2(oacc[n][2], oacc[n][3]);
    }
  }
  if (gc == 0) {
    red[wk*64 + r0]     = psum[0];
    red[wk*64 + r0 + 8] = psum[1];
  }
  __syncthreads();
  if (wk == 0) {
    float L0 = red[r0]     + red[64 + r0];
    float L1 = red[r0 + 8] + red[64 + r0 + 8];
#pragma unroll
    for (int n = 0; n < 16; n++) {
      int col = n*8 + 2*gc;
      float2 x0 = *(const float2*)(OX + (r0  )*132 + col);
      float2 x1 = *(const float2*)(OX + (r0+8)*132 + col);
      oacc[n][0] += x0.x; oacc[n][1] += x0.y;
      oacc[n][2] += x1.x; oacc[n][3] += x1.y;
    }
    if (mode < 3) {
      float iv0 = 1.0f / L0, iv1 = 1.0f / L1;
#pragma unroll
      for (int n = 0; n < 16; n++) {
        int col = n*8 + 2*gc;
        *(float2*)(dO + (((size_t)bh*nq + q0 + r0  ) << 7) + col) =
            make_float2(oacc[n][0]*iv0, oacc[n][1]*iv0);
        *(float2*)(dO + (((size_t)bh*nq + q0 + r0+8) << 7) + col) =
            make_float2(oacc[n][2]*iv1, oacc[n][3]*iv1);
      }
      if (gc == 0) {
        dL[(size_t)bh*nq + q0 + r0]     = logf(L0);
        dL[(size_t)bh*nq + q0 + r0 + 8] = logf(L1);
      }
    } else {
      size_t pb = (size_t)(sp*BH_ + bh)*320 + q0;
#pragma unroll
      for (int n = 0; n < 16; n++) {
        int col = n*8 + 2*gc;
        *(float2*)(g_part_o + ((pb + r0  ) << 7) + col) = make_float2(oacc[n][0], oacc[n][1]);
        *(float2*)(g_part_o + ((pb + r0+8) << 7) + col) = make_float2(oacc[n][2], oacc[n][3]);
      }
      if (gc == 0) {
        g_part_l[pb + r0]     = L0;
        g_part_l[pb + r0 + 8] = L1;
      }
    }
  }
}

// ---------------- p1 combine + broadcast (runs BEFORE merge-scatter) ----------------
__global__ void __launch_bounds__(256) combine_kernel(float* __restrict__ out, int has_lse) {
  unsigned wi = (blockIdx.x * 256u + threadIdx.x) >> 5;
  int lane = threadIdx.x & 31;
  int bh = wi >> 10, j = wi & 1023;
  float l1 = g_lse1[wi] + LN8_F;
  float ld = g_ldel[wi];
  float la = g_ladd[wi];
  float c1 = expf(ld - l1);
  float inv1 = 1.0f / (1.0f - c1);
  float lp1 = l1 + log1pf(-c1);
  float c2 = 1.0f / (1.0f + expf(la - lp1));
  float lse = fmaxf(lp1, la) + log1pf(expf(-fabsf(lp1 - la)));
  size_t off = ((size_t)wi << 7) + lane*4;
  float4 a0 = *(const float4*)(g_attn1 + off);
  float4 ad = *(const float4*)(g_adel + off);
  float4 aa = *(const float4*)(g_aadd + off);
  float4 r;
  float c2b = 1.0f - c2;
  r.x = c2*((a0.x - c1*ad.x)*inv1) + c2b*aa.x;
  r.y = c2*((a0.y - c1*ad.y)*inv1) + c2b*aa.y;
  r.z = c2*((a0.z - c1*ad.z)*inv1) + c2b*aa.z;
  r.w = c2*((a0.w - c1*ad.w)*inv1) + c2b*aa.w;
  float* outl = out + (size_t)BH_*NTOK*D_;
#pragma unroll
  for (int g = 0; g < G_; g++) {
    size_t orow = (size_t)bh*NTOK + g*P_ + j;
    *(float4*)(out + (orow << 7) + lane*4) = r;
    if (lane == 0 && has_lse) outl[orow] = lse;
  }
}

// ---------------- fused p2 merge + scatter (overwrites sampled rows) ----------------
__global__ void __launch_bounds__(256) merge_scatter_kernel(float* __restrict__ out, int has_lse) {
  int bh = blockIdx.y;
  int w = threadIdx.x >> 5, lane = threadIdx.x & 31;
  int row = blockIdx.x*8 + w;
  if (row >= S_) return;
  float L = 0.f;
  float4 o = make_float4(0,0,0,0);
#pragma unroll
  for (int s = 0; s < 8; s++) {
    size_t ri = (size_t)(s*BH_ + bh)*320 + row;
    L += g_part_l[ri];
    float4 po = *(const float4*)(g_part_o + (ri << 7) + lane*4);
    o.x += po.x; o.y += po.y; o.z += po.z; o.w += po.w;
  }
  float inv = 1.0f / L;
  o.x*=inv; o.y*=inv; o.z*=inv; o.w*=inv;
  int g = row / MK_, tt = row % MK_;
  int qj = g_qidx[(bh*G_+g)*MK_+tt];
  size_t orow = (size_t)bh*NTOK + g*P_ + qj;
  *(float4*)(out + (orow << 7) + lane*4) = o;
  if (lane == 0 && has_lse) out[(size_t)BH_*NTOK*D_ + orow] = logf(L);
}

// ---------------- launch ----------------
extern "C" void kernel_launch(void* const* d_in, const int* in_sizes, int n_in,
                              void* d_out, int out_size) {
  const float* q = (const float*)d_in[0];
  const float* k = (const float*)d_in[1];
  const float* v = (const float*)d_in[2];
  float* out = (float*)d_out;
  int has_lse = (out_size >= BH_*NTOK*(D_ + 1)) ? 1 : 0;

  cudaFuncSetAttribute(attn_bf16_kernel,
                       cudaFuncAttributeMaxDynamicSharedMemorySize, SMEM_B);

  prep_kernel  <<<4096, 256>>>(q, k, v);
  topk_kernel  <<<dim3(BH_*G_, 2), 256>>>();
  gather_kernel<<<(BH_*S_*32 + 255)/256, 256>>>(q, k, v);

  attn_bf16_kernel<<<88*BH_, 256, SMEM_B>>>(k, v);

  combine_kernel<<<(BH_*P_*32)/256, 256>>>(out, has_lse);
  merge_scatter_kernel<<<dim3((S_+7)/8, BH_), 256>>>(out, has_lse);
}

// round 17
// speedup vs baseline: 1.6154x; 1.0083x over previous
#include <cuda_runtime.h>
#include <cuda_bf16.h>
#include <stdint.h>
#include <math.h>

#define B_    2
#define H_    16
#define NTOK  8192
#define D_    128
#define G_    8
#define P_    1024
#define MK_   34
#define S_    (G_*MK_)
#define BH_   (B_*H_)

#define SCALE_F 0.08838834764831843f
#define LN8_F   2.0794415416798357f
#define TINY_F  1.17549435e-38f
#define EPS_F   1.1920929e-07f

// smem u32 offsets (split hi/lo arrays; OX/red alias dead regions at epilogue)
#define U_QH 0
#define U_QL 4096
#define U_KH 8192
#define U_KL 12288
#define U_VH 16384
#define U_VL 20480
#define SMEM_U 24576
#define SMEM_B (SMEM_U*4)

__device__ __align__(16) float g_qrep [BH_*P_*D_];
__device__ __align__(16) float g_krep [BH_*P_*D_];
__device__ __align__(16) float g_vmean[BH_*P_*D_];
__device__ __align__(16) float g_attn1[BH_*P_*D_];
__device__ __align__(16) float g_adel [BH_*P_*D_];
__device__ __align__(16) float g_aadd [BH_*P_*D_];
__device__ float g_lse1[BH_*P_];
__device__ float g_ldel[BH_*P_];
__device__ float g_ladd[BH_*P_];
__device__ float g_score_k[BH_*G_*P_];
__device__ float g_score_q[BH_*G_*P_];
__device__ int   g_kidx[BH_*G_*MK_];
__device__ int   g_qidx[BH_*G_*MK_];
__device__ __align__(16) float g_ksub   [BH_*S_*D_];
__device__ __align__(16) float g_krepsub[BH_*S_*D_];
__device__ __align__(16) float g_vsub   [BH_*S_*D_];
__device__ __align__(16) float g_qsub   [BH_*S_*D_];
__device__ float g_l2[BH_*S_];
__device__ __align__(16) float g_part_o[(size_t)8*BH_*320*D_];
__device__ float g_part_l[8*BH_*320];

__device__ __forceinline__ void split2(float x0, float x1, uint32_t& hp, uint32_t& lp) {
  __nv_bfloat162 h = __floats2bfloat162_rn(x0, x1);
  hp = *reinterpret_cast<uint32_t*>(&h);
  float h0 = __uint_as_float(hp << 16);
  float h1 = __uint_as_float(hp & 0xffff0000u);
  __nv_bfloat162 l = __floats2bfloat162_rn(x0 - h0, x1 - h1);
  lp = *reinterpret_cast<uint32_t*>(&l);
}

#define MMAB(d,a,b0,b1) \
  asm volatile("mma.sync.aligned.m16n8k16.row.col.f32.bf16.bf16.f32 " \
  "{%0,%1,%2,%3},{%4,%5,%6,%7},{%8,%9},{%0,%1,%2,%3};" \
  : "+f"((d)[0]),"+f"((d)[1]),"+f"((d)[2]),"+f"((d)[3]) \
  : "r"((a)[0]),"r"((a)[1]),"r"((a)[2]),"r"((a)[3]),"r"(b0),"r"(b1))

// ---------------- threefry2x32 ----------------
__device__ __forceinline__ void threefry2x32(uint32_t k0, uint32_t k1,
                                             uint32_t x0, uint32_t x1,
                                             uint32_t& o0, uint32_t& o1) {
  uint32_t k2 = k0 ^ k1 ^ 0x1BD11BDAu;
  x0 += k0; x1 += k1;
#define TFR(r) { x0 += x1; x1 = (x1 << (r)) | (x1 >> (32 - (r))); x1 ^= x0; }
  TFR(13) TFR(15) TFR(26) TFR(6)   x0 += k1; x1 += k2 + 1u;
  TFR(17) TFR(29) TFR(16) TFR(24)  x0 += k2; x1 += k0 + 2u;
  TFR(13) TFR(15) TFR(26) TFR(6)   x0 += k0; x1 += k1 + 3u;
  TFR(17) TFR(29) TFR(16) TFR(24)  x0 += k1; x1 += k2 + 4u;
  TFR(13) TFR(15) TFR(26) TFR(6)   x0 += k2; x1 += k0 + 5u;
#undef TFR
  o0 = x0; o1 = x1;
}

// ---------------- fused means + scores ----------------
__global__ void __launch_bounds__(256) prep_kernel(const float* __restrict__ q,
                                                   const float* __restrict__ k,
                                                   const float* __restrict__ v) {
  int wid = (blockIdx.x*256 + threadIdx.x) >> 5;
  int lane = threadIdx.x & 31;
  int bh = wid >> 10, j = wid & 1023;
  size_t base = (((size_t)bh*NTOK) << 7) + (((size_t)j) << 7) + lane*4;
  size_t rbase = ((((size_t)bh*P_) + j) << 7) + lane*4;
  float4 rows[8];
  float kss = 0.f, qss = 0.f;

  float4 mn = make_float4(0,0,0,0);
#pragma unroll
  for (int g = 0; g < 8; g++) {
    rows[g] = *(const float4*)(k + base + ((size_t)g*P_ << 7));
    mn.x+=rows[g].x; mn.y+=rows[g].y; mn.z+=rows[g].z; mn.w+=rows[g].w;
  }
  mn.x*=0.125f; mn.y*=0.125f; mn.z*=0.125f; mn.w*=0.125f;
  *(float4*)(g_krep + rbase) = mn;
#pragma unroll
  for (int g = 0; g < 8; g++) {
    float dx=rows[g].x-mn.x, dy=rows[g].y-mn.y, dz=rows[g].z-mn.z, dw=rows[g].w-mn.w;
    float ss = dx*dx + dy*dy + dz*dz + dw*dw;
#pragma unroll
    for (int off = 16; off; off >>= 1) ss += __shfl_xor_sync(0xffffffffu, ss, off);
    if (lane == g) kss = ss;
  }
  mn = make_float4(0,0,0,0);
#pragma unroll
  for (int g = 0; g < 8; g++) {
    rows[g] = *(const float4*)(q + base + ((size_t)g*P_ << 7));
    mn.x+=rows[g].x; mn.y+=rows[g].y; mn.z+=rows[g].z; mn.w+=rows[g].w;
  }
  mn.x*=0.125f; mn.y*=0.125f; mn.z*=0.125f; mn.w*=0.125f;
  *(float4*)(g_qrep + rbase) = mn;
#pragma unroll
  for (int g = 0; g < 8; g++) {
    float dx=rows[g].x-mn.x, dy=rows[g].y-mn.y, dz=rows[g].z-mn.z, dw=rows[g].w-mn.w;
    float ss = dx*dx + dy*dy + dz*dz + dw*dw;
#pragma unroll
    for (int off = 16; off; off >>= 1) ss += __shfl_xor_sync(0xffffffffu, ss, off);
    if (lane == 8 + g) qss = ss;
  }
  mn = make_float4(0,0,0,0);
#pragma unroll
  for (int g = 0; g < 8; g++) {
    float4 r = *(const float4*)(v + base + ((size_t)g*P_ << 7));
    mn.x+=r.x; mn.y+=r.y; mn.z+=r.z; mn.w+=r.w;
  }
  mn.x*=0.125f; mn.y*=0.125f; mn.z*=0.125f; mn.w*=0.125f;
  *(float4*)(g_vmean + rbase) = mn;

  if (lane < 16) {
    int t = lane >> 3, g = lane & 7;
    float ss = t ? qss : kss;
    unsigned r = (unsigned)(bh*8192 + g*1024 + j);
    uint32_t rk0, rk1, o0, o1;
    threefry2x32(0u, 42u, 0u, (uint32_t)t, rk0, rk1);
    threefry2x32(rk0, rk1, 0u, r, o0, o1);
    uint32_t bits = o0 ^ o1;
    float u = __uint_as_float((bits >> 9) | 0x3f800000u) - 1.0f;
    if (u <= 0.0f) u = TINY_F;
    float gum = -logf(-logf(u));
    float score = logf(sqrtf(ss) * 100.0f + EPS_F) + gum;
    (t ? g_score_q : g_score_k)[r] = score;
  }
}

// ---------------- top-34 ----------------
__global__ void __launch_bounds__(256) topk_kernel() {
  int grp = blockIdx.x;
  int t   = blockIdx.y;
  float* sc = (t ? g_score_q : g_score_k) + (size_t)grp * P_;
  int*  out = (t ? g_qidx    : g_kidx   ) + (size_t)grp * MK_;
  __shared__ float sv[1024];
  __shared__ float rv[256];
  __shared__ int   ri[256];
  int tid = threadIdx.x;
#pragma unroll
  for (int r = 0; r < 4; r++) sv[tid + 256*r] = sc[tid + 256*r];
  __syncthreads();
  for (int it = 0; it < MK_; it++) {
    float bv = -INFINITY; int bi = 0x7fffffff;
#pragma unroll
    for (int r = 0; r < 4; r++) {
      int i = tid + 256*r;
      float vv = sv[i];
      if (vv > bv || (vv == bv && i < bi)) { bv = vv; bi = i; }
    }
    rv[tid] = bv; ri[tid] = bi;
    __syncthreads();
    for (int s = 128; s; s >>= 1) {
      if (tid < s) {
        float vv = rv[tid+s]; int i2 = ri[tid+s];
        if (vv > rv[tid] || (vv == rv[tid] && i2 < ri[tid])) { rv[tid]=vv; ri[tid]=i2; }
      }
      __syncthreads();
    }
    if (tid == 0) { out[it] = ri[0]; sv[ri[0]] = -INFINITY; }
    __syncthreads();
  }
}

// ---------------- gathers ----------------
__global__ void __launch_bounds__(256) gather_kernel(const float* __restrict__ q,
                                                     const float* __restrict__ k,
                                                     const float* __restrict__ v) {
  unsigned wi = (blockIdx.x * 256u + threadIdx.x) >> 5;
  int lane = threadIdx.x & 31;
  if (wi >= (unsigned)(BH_*S_)) return;
  int bh = wi / S_;
  int rr = wi % S_;
  int g = rr / MK_, tt = rr % MK_;
  int kj = g_kidx[(bh*G_+g)*MK_+tt];
  int qj = g_qidx[(bh*G_+g)*MK_+tt];
  size_t srck = ((size_t)bh*NTOK + g*P_ + kj) << 7;
  size_t srcq = ((size_t)bh*NTOK + g*P_ + qj) << 7;
  size_t dst  = ((size_t)wi << 7) + lane*4;
  *(float4*)(g_ksub    + dst) = *(const float4*)(k + srck + lane*4);
  *(float4*)(g_vsub    + dst) = *(const float4*)(v + srck + lane*4);
  *(float4*)(g_krepsub + dst) = *(const float4*)(g_krep + (((size_t)bh*P_ + kj) << 7) + lane*4);
  *(float4*)(g_qsub    + dst) = *(const float4*)(q + srcq + lane*4);
}

// ---------------- bf16x3 mma flash attention, P in registers ----------------
// per bh: j in [0,40) p2 (sp=j/5, qb=j%5); [40,56) p0; [56,72) p1-del; [72,88) p1-add
__global__ void __launch_bounds__(256, 2)
attn_bf16_kernel(const float* __restrict__ kin, const float* __restrict__ vin) {
  extern __shared__ uint32_t su[];
  uint32_t* Qh = su + U_QH; uint32_t* Ql = su + U_QL;
  uint32_t* Kh = su + U_KH; uint32_t* Kl = su + U_KL;
  uint32_t* Vth = su + U_VH; uint32_t* Vtl = su + U_VL;

  int tid = threadIdx.x;
  int w = tid >> 5, lane = tid & 31;
  int gr = lane >> 2, gc = lane & 3;
  int wq = w >> 1, wk = w & 1;
  int cx3 = gr & 3;

  int bh = blockIdx.x / 88;
  int j  = blockIdx.x % 88;
  int mode, qb, sp = 0;
  if (j < 40) { mode = 3; sp = j / 5; qb = j % 5; }
  else { mode = (j - 40) >> 4; qb = (j - 40) & 15; }

  const float *Qs, *Ks, *Vs; float *dO, *dL;
  int nq, ke, ntile, k0;
  if (mode == 0) { Qs=g_qrep+(size_t)bh*P_*D_; Ks=g_krep+(size_t)bh*P_*D_;  Vs=g_vmean+(size_t)bh*P_*D_;
                   nq=P_; ke=P_; ntile=16; k0=0; dO=g_attn1; dL=g_lse1; }
  else if (mode==1){Qs=g_qrep+(size_t)bh*P_*D_; Ks=g_krepsub+(size_t)bh*S_*D_; Vs=g_vsub+(size_t)bh*S_*D_;
                   nq=P_; ke=S_; ntile=5; k0=0; dO=g_adel; dL=g_ldel; }
  else if (mode==2){Qs=g_qrep+(size_t)bh*P_*D_; Ks=g_ksub+(size_t)bh*S_*D_;  Vs=g_vsub+(size_t)bh*S_*D_;
                   nq=P_; ke=S_; ntile=5; k0=0; dO=g_aadd; dL=g_ladd; }
  else           { Qs=g_qsub+(size_t)bh*S_*D_; Ks=kin+(size_t)bh*NTOK*D_;   Vs=vin+(size_t)bh*NTOK*D_;
                   nq=S_; k0=sp*1024; ke=k0+1024; ntile=16; dO=0; dL=0; }
  int q0 = qb * 64;

  // ---- stage Q hi/lo ----
#pragma unroll
  for (int t = 0; t < 8; t++) {
    int lin = tid + t*256;
    int row = lin >> 5, c4 = lin & 31;
    int gq = q0 + row; if (gq > nq-1) gq = nq-1;
    float4 v = *(const float4*)(Qs + ((size_t)gq << 7) + c4*4);
    v.x*=SCALE_F; v.y*=SCALE_F; v.z*=SCALE_F; v.w*=SCALE_F;
    uint32_t hp0,lp0,hp1,lp1;
    split2(v.x, v.y, hp0, lp0);
    split2(v.z, v.w, hp1, lp1);
    int r7 = row & 7;
    int j0 = 2*c4, j1 = j0+1;
    int col0 = (((j0>>3) ^ r7)<<3) + ((j0&3)<<1) + ((j0>>2)&1);
    int col1 = (((j1>>3) ^ r7)<<3) + ((j1&3)<<1) + ((j1>>2)&1);
    Qh[row*64+col0]=hp0; Ql[row*64+col0]=lp0;
    Qh[row*64+col1]=hp1; Ql[row*64+col1]=lp1;
  }

  float oacc[16][4];
#pragma unroll
  for (int n=0;n<16;n++)
#pragma unroll
    for (int t=0;t<4;t++) oacc[n][t]=0.f;
  float psum[2] = {0.f, 0.f};

  int r0 = wq*16 + gr;
  int srow = tid >> 5;          // this thread's staged K row
  int sc4  = tid & 31;          // this thread's staged K col group

  for (int tile = 0; tile < ntile; tile++) {
    int kb = k0 + tile*64;
    // ---- K global loads BEFORE barrier (latency overlapped with barrier wait) ----
    float4 kreg[8];
#pragma unroll
    for (int t = 0; t < 8; t++) {
      int gk = kb + srow + t*8;
      kreg[t] = make_float4(0.f,0.f,0.f,0.f);
      if (gk < ke) kreg[t] = *(const float4*)(Ks + ((size_t)gk << 7) + sc4*4);
    }
    __syncthreads();
    // ---- K split/STS ----
#pragma unroll
    for (int t = 0; t < 8; t++) {
      int row = srow + t*8;
      uint32_t hp0,lp0,hp1,lp1;
      split2(kreg[t].x, kreg[t].y, hp0, lp0);
      split2(kreg[t].z, kreg[t].w, hp1, lp1);
      int r7 = row & 7;
      int j0 = 2*sc4, j1 = j0+1;
      int col0 = (((j0>>3) ^ r7)<<3) + ((j0&3)<<1) + ((j0>>2)&1);
      int col1 = (((j1>>3) ^ r7)<<3) + ((j1&3)<<1) + ((j1>>2)&1);
      Kh[row*64+col0]=hp0; Kl[row*64+col0]=lp0;
      Kh[row*64+col1]=hp1; Kl[row*64+col1]=lp1;
    }
    // ---- V stage ----
#pragma unroll
    for (int t = 0; t < 4; t++) {
      int lin = tid + t*256;
      int kp = lin & 31, dg = lin >> 5;
      int d0 = dg*4;
      int ka = kb + 2*kp;
      float4 va = make_float4(0,0,0,0), vb = va;
      if (ka   < ke) va = *(const float4*)(Vs + ((size_t)ka << 7) + d0);
      if (ka+1 < ke) vb = *(const float4*)(Vs + ((size_t)(ka+1) << 7) + d0);
      int cc = kp>>3, gg = kp&3, hh = (kp>>2)&1;
      uint32_t hp, lp;
      split2(va.x, vb.x, hp, lp);
      Vth[(d0+0)*32 + (((cc^0)<<3)+(gg<<1)+hh)] = hp; Vtl[(d0+0)*32 + (((cc^0)<<3)+(gg<<1)+hh)] = lp;
      split2(va.y, vb.y, hp, lp);
      Vth[(d0+1)*32 + (((cc^1)<<3)+(gg<<1)+hh)] = hp; Vtl[(d0+1)*32 + (((cc^1)<<3)+(gg<<1)+hh)] = lp;
      split2(va.z, vb.z, hp, lp);
      Vth[(d0+2)*32 + (((cc^2)<<3)+(gg<<1)+hh)] = hp; Vtl[(d0+2)*32 + (((cc^2)<<3)+(gg<<1)+hh)] = lp;
      split2(va.w, vb.w, hp, lp);
      Vth[(d0+3)*32 + (((cc^3)<<3)+(gg<<1)+hh)] = hp; Vtl[(d0+3)*32 + (((cc^3)<<3)+(gg<<1)+hh)] = lp;
    }
    __syncthreads();

    // ---- S = Q K^T (16q x 32k per warp, 3-pass) ----
    float sacc[4][4];
#pragma unroll
    for (int n=0;n<4;n++)
#pragma unroll
      for (int t=0;t<4;t++) sacc[n][t]=0.f;
#pragma unroll
    for (int c = 0; c < 8; c++) {
      int cq = ((c ^ gr) << 3) + (gc << 1);
      uint2 a0h = *(const uint2*)(Qh + (r0  )*64 + cq);
      uint2 a1h = *(const uint2*)(Qh + (r0+8)*64 + cq);
      uint2 a0l = *(const uint2*)(Ql + (r0  )*64 + cq);
      uint2 a1l = *(const uint2*)(Ql + (r0+8)*64 + cq);
      uint32_t Ah[4] = {a0h.x, a1h.x, a0h.y, a1h.y};
      uint32_t Al[4] = {a0l.x, a1l.x, a0l.y, a1l.y};
#pragma unroll
      for (int nn = 0; nn < 4; nn++) {
        int nb = wk*32 + nn*8 + gr;
        uint2 bh2 = *(const uint2*)(Kh + nb*64 + cq);
        uint2 bl2 = *(const uint2*)(Kl + nb*64 + cq);
        MMAB(sacc[nn], Ah, bh2.x, bh2.y);
        MMAB(sacc[nn], Ah, bl2.x, bl2.y);
        MMAB(sacc[nn], Al, bh2.x, bh2.y);
      }
    }

    // ---- exp in registers -> P fragments (natural order IS A-frag order) ----
    uint32_t Phi[2][4], Plo[2][4];
#pragma unroll
    for (int kc = 0; kc < 2; kc++) {
#pragma unroll
      for (int hh = 0; hh < 2; hh++) {
        int nn = 2*kc + hh;
        int colb = kb + wk*32 + nn*8 + 2*gc;
        float p0 = (colb   < ke) ? __expf(sacc[nn][0]) : 0.f;
        float p1 = (colb+1 < ke) ? __expf(sacc[nn][1]) : 0.f;
        float p2 = (colb   < ke) ? __expf(sacc[nn][2]) : 0.f;
        float p3 = (colb+1 < ke) ? __expf(sacc[nn][3]) : 0.f;
        psum[0] += p0 + p1;
        psum[1] += p2 + p3;
        split2(p0, p1, Phi[kc][2*hh+0], Plo[kc][2*hh+0]);
        split2(p2, p3, Phi[kc][2*hh+1], Plo[kc][2*hh+1]);
      }
    }

    // ---- O += P V (partial over this warp's 32 keys, 3-pass) ----
#pragma unroll
    for (int kc = 0; kc < 2; kc++) {
      int c2 = wk*2 + kc;
      int cp = (((c2 ^ cx3) & 3) << 3) + (gc << 1);
#pragma unroll
      for (int n = 0; n < 16; n++) {
        int dn = n*8 + gr;
        uint2 vh = *(const uint2*)(Vth + dn*32 + cp);
        uint2 vl = *(const uint2*)(Vtl + dn*32 + cp);
        MMAB(oacc[n], Phi[kc], vh.x, vh.y);
        MMAB(oacc[n], Phi[kc], vl.x, vl.y);
        MMAB(oacc[n], Plo[kc], vh.x, vh.y);
      }
    }
  }

  // ---- cross-wk reduction + epilogue ----
  psum[0] += __shfl_xor_sync(0xffffffffu, psum[0], 1);
  psum[0] += __shfl_xor_sync(0xffffffffu, psum[0], 2);
  psum[1] += __shfl_xor_sync(0xffffffffu, psum[1], 1);
  psum[1] += __shfl_xor_sync(0xffffffffu, psum[1], 2);
  __syncthreads();
  float* OX  = (float*)su;               // 64 x 132 (aliases dead Q/K head)
  float* red = (float*)(su + U_VH);      // 2 x 64   (aliases dead V)
  if (wk == 1) {
#pragma unroll
    for (int n = 0; n < 16; n++) {
      int col = n*8 + 2*gc;
      *(float2*)(OX + (r0  )*132 + col) = make_float2(oacc[n][0], oacc[n][1]);
      *(float2*)(OX + (r0+8)*132 + col) = make_float2(oacc[n][2], oacc[n][3]);
    }
  }
  if (gc == 0) {
    red[wk*64 + r0]     = psum[0];
    red[wk*64 + r0 + 8] = psum[1];
  }
  __syncthreads();
  if (wk == 0) {
    float L0 = red[r0]     + red[64 + r0];
    float L1 = red[r0 + 8] + red[64 + r0 + 8];
#pragma unroll
    for (int n = 0; n < 16; n++) {
      int col = n*8 + 2*gc;
      float2 x0 = *(const float2*)(OX + (r0  )*132 + col);
      float2 x1 = *(const float2*)(OX + (r0+8)*132 + col);
      oacc[n][0] += x0.x; oacc[n][1] += x0.y;
      oacc[n][2] += x1.x; oacc[n][3] += x1.y;
    }
    if (mode < 3) {
      float iv0 = 1.0f / L0, iv1 = 1.0f / L1;
#pragma unroll
      for (int n = 0; n < 16; n++) {
        int col = n*8 + 2*gc;
        *(float2*)(dO + (((size_t)bh*nq + q0 + r0  ) << 7) + col) =
            make_float2(oacc[n][0]*iv0, oacc[n][1]*iv0);
        *(float2*)(dO + (((size_t)bh*nq + q0 + r0+8) << 7) + col) =
            make_float2(oacc[n][2]*iv1, oacc[n][3]*iv1);
      }
      if (gc == 0) {
        dL[(size_t)bh*nq + q0 + r0]     = logf(L0);
        dL[(size_t)bh*nq + q0 + r0 + 8] = logf(L1);
      }
    } else {
      size_t pb = (size_t)(sp*BH_ + bh)*320 + q0;
#pragma unroll
      for (int n = 0; n < 16; n++) {
        int col = n*8 + 2*gc;
        *(float2*)(g_part_o + ((pb + r0  ) << 7) + col) = make_float2(oacc[n][0], oacc[n][1]);
        *(float2*)(g_part_o + ((pb + r0+8) << 7) + col) = make_float2(oacc[n][2], oacc[n][3]);
      }
      if (gc == 0) {
        g_part_l[pb + r0]     = L0;
        g_part_l[pb + r0 + 8] = L1;
      }
    }
  }
}

// ---------------- p1 combine + broadcast (runs BEFORE merge-scatter) ----------------
__global__ void __launch_bounds__(256) combine_kernel(float* __restrict__ out, int has_lse) {
  unsigned wi = (blockIdx.x * 256u + threadIdx.x) >> 5;
  int lane = threadIdx.x & 31;
  int bh = wi >> 10, j = wi & 1023;
  float l1 = g_lse1[wi] + LN8_F;
  float ld = g_ldel[wi];
  float la = g_ladd[wi];
  float c1 = expf(ld - l1);
  float inv1 = 1.0f / (1.0f - c1);
  float lp1 = l1 + log1pf(-c1);
  float c2 = 1.0f / (1.0f + expf(la - lp1));
  float lse = fmaxf(lp1, la) + log1pf(expf(-fabsf(lp1 - la)));
  size_t off = ((size_t)wi << 7) + lane*4;
  float4 a0 = *(const float4*)(g_attn1 + off);
  float4 ad = *(const float4*)(g_adel + off);
  float4 aa = *(const float4*)(g_aadd + off);
  float4 r;
  float c2b = 1.0f - c2;
  r.x = c2*((a0.x - c1*ad.x)*inv1) + c2b*aa.x;
  r.y = c2*((a0.y - c1*ad.y)*inv1) + c2b*aa.y;
  r.z = c2*((a0.z - c1*ad.z)*inv1) + c2b*aa.z;
  r.w = c2*((a0.w - c1*ad.w)*inv1) + c2b*aa.w;
  float* outl = out + (size_t)BH_*NTOK*D_;
#pragma unroll
  for (int g = 0; g < G_; g++) {
    size_t orow = (size_t)bh*NTOK + g*P_ + j;
    *(float4*)(out + (orow << 7) + lane*4) = r;
    if (lane == 0 && has_lse) outl[orow] = lse;
  }
}

// ---------------- fused p2 merge + scatter (overwrites sampled rows) ----------------
__global__ void __launch_bounds__(256) merge_scatter_kernel(float* __restrict__ out, int has_lse) {
  int bh = blockIdx.y;
  int w = threadIdx.x >> 5, lane = threadIdx.x & 31;
  int row = blockIdx.x*8 + w;
  if (row >= S_) return;
  float L = 0.f;
  float4 o = make_float4(0,0,0,0);
#pragma unroll
  for (int s = 0; s < 8; s++) {
    size_t ri = (size_t)(s*BH_ + bh)*320 + row;
    L += g_part_l[ri];
    float4 po = *(const float4*)(g_part_o + (ri << 7) + lane*4);
    o.x += po.x; o.y += po.y; o.z += po.z; o.w += po.w;
  }
  float inv = 1.0f / L;
  o.x*=inv; o.y*=inv; o.z*=inv; o.w*=inv;
  int g = row / MK_, tt = row % MK_;
  int qj = g_qidx[(bh*G_+g)*MK_+tt];
  size_t orow = (size_t)bh*NTOK + g*P_ + qj;
  *(float4*)(out + (orow << 7) + lane*4) = o;
  if (lane == 0 && has_lse) out[(size_t)BH_*NTOK*D_ + orow] = logf(L);
}

// ---------------- launch ----------------
extern "C" void kernel_launch(void* const* d_in, const int* in_sizes, int n_in,
                              void* d_out, int out_size) {
  const float* q = (const float*)d_in[0];
  const float* k = (const float*)d_in[1];
  const float* v = (const float*)d_in[2];
  float* out = (float*)d_out;
  int has_lse = (out_size >= BH_*NTOK*(D_ + 1)) ? 1 : 0;

  cudaFuncSetAttribute(attn_bf16_kernel,
                       cudaFuncAttributeMaxDynamicSharedMemorySize, SMEM_B);

  prep_kernel  <<<4096, 256>>>(q, k, v);
  topk_kernel  <<<dim3(BH_*G_, 2), 256>>>();
  gather_kernel<<<(BH_*S_*32 + 255)/256, 256>>>(q, k, v);

  attn_bf16_kernel<<<88*BH_, 256, SMEM_B>>>(k, v);

  combine_kernel<<<(BH_*P_*32)/256, 256>>>(out, has_lse);
  merge_scatter_kernel<<<dim3((S_+7)/8, BH_), 256>>>(out, has_lse);
}